// round 1
// baseline (speedup 1.0000x reference)
#include <cuda_runtime.h>

// SIREN forward: N points, 3 -> 5 (sine) -> 256 x [5 -> 5 (sine)] -> 1 (linear)
// Output buffer: [out (N floats) | coords passthrough (3N floats)]

static constexpr int IN_F  = 3;
static constexpr int HID   = 5;
static constexpr int N_HID = 256;
static constexpr float OMEGA = 30.0f;
static constexpr int TPB = 256;

// Accurate fp32 sine, pure FMA-pipe (no MUFU), valid for |x| <~ 1e4.
// Cody-Waite pi/2 reduction + fdlibm-grade minimax sin/cos kernels.
__device__ __forceinline__ float sin_acc(float x) {
    float fj = rintf(x * 0.6366197723675814f);   // x * 2/pi, round to nearest
    int   q  = (int)fj;
    float r  = fmaf(fj, -1.5707962513e+00f, x);  // pi/2 hi
    r        = fmaf(fj, -7.5497894159e-08f, r);  // pi/2 mid
    r        = fmaf(fj, -5.3903029534e-15f, r);  // pi/2 lo
    float r2 = r * r;
    // sin kernel (|r| <= pi/4)
    float ps = fmaf(r2,  2.7183114939898219e-06f, -1.9839334836096632e-04f);
    ps       = fmaf(r2, ps,  8.3333293858894632e-03f);
    ps       = fmaf(r2, ps, -1.6666666641626524e-01f);
    float s  = fmaf(r * r2, ps, r);
    // cos kernel
    float pc = fmaf(r2,  2.4390448796277409e-05f, -1.3886763774609929e-03f);
    pc       = fmaf(r2, pc,  4.1666623323739063e-02f);
    pc       = fmaf(r2, pc, -4.9999999725103100e-01f);
    float c  = fmaf(r2, pc, 1.0f);
    float res = (q & 1) ? c : s;
    // flip sign for quadrants 2,3
    return __uint_as_float(__float_as_uint(res) ^ ((unsigned)(q & 2) << 30));
}

__global__ void __launch_bounds__(TPB)
siren_kernel(const float* __restrict__ coords,
             const float* __restrict__ Wf, const float* __restrict__ bf,
             const float* __restrict__ Wh, const float* __restrict__ bh,
             const float* __restrict__ Wl, const float* __restrict__ bl,
             float* __restrict__ out, int N)
{
    // per-layer blob: 25 weights + 5 biases, stride 32 (all pre-scaled by OMEGA)
    __shared__ float sw[N_HID * 32];
    __shared__ float sfirst[20];   // 15 W_first + 5 b_first, pre-scaled by OMEGA
    __shared__ float sfinal[6];    // 5 W_final + b_final, NOT scaled

    const int tid = threadIdx.x;
    for (int idx = tid; idx < N_HID * 25; idx += TPB) {
        sw[(idx / 25) * 32 + (idx % 25)] = OMEGA * Wh[idx];
    }
    for (int idx = tid; idx < N_HID * 5; idx += TPB) {
        sw[(idx / 5) * 32 + 25 + (idx % 5)] = OMEGA * bh[idx];
    }
    if (tid < 15) sfirst[tid]      = OMEGA * Wf[tid];
    if (tid < 5)  sfirst[15 + tid] = OMEGA * bf[tid];
    if (tid < 5)  sfinal[tid]      = Wl[tid];
    if (tid == 0) sfinal[5]        = bl[0];
    __syncthreads();

    const int i = blockIdx.x * TPB + tid;
    if (i >= N) return;

    const float c0 = coords[3 * i + 0];
    const float c1 = coords[3 * i + 1];
    const float c2 = coords[3 * i + 2];

    float x[HID];
#pragma unroll
    for (int j = 0; j < HID; j++) {
        float y = sfirst[15 + j];
        y = fmaf(sfirst[j * IN_F + 0], c0, y);
        y = fmaf(sfirst[j * IN_F + 1], c1, y);
        y = fmaf(sfirst[j * IN_F + 2], c2, y);
        x[j] = sin_acc(y);
    }

#pragma unroll 1
    for (int l = 0; l < N_HID; l++) {
        const float* __restrict__ L = &sw[l * 32];
        float y[HID];
#pragma unroll
        for (int j = 0; j < HID; j++) y[j] = L[25 + j];
#pragma unroll
        for (int k = 0; k < HID; k++) {
            const float xv = x[k];
#pragma unroll
            for (int j = 0; j < HID; j++) y[j] = fmaf(L[j * HID + k], xv, y[j]);
        }
#pragma unroll
        for (int j = 0; j < HID; j++) x[j] = sin_acc(y[j]);
    }

    float o = sfinal[5];
#pragma unroll
    for (int j = 0; j < HID; j++) o = fmaf(sfinal[j], x[j], o);
    out[i] = o;

    // coords passthrough (second tuple element)
    float* __restrict__ cp = out + N;
    cp[3 * i + 0] = c0;
    cp[3 * i + 1] = c1;
    cp[3 * i + 2] = c2;
}

extern "C" void kernel_launch(void* const* d_in, const int* in_sizes, int n_in,
                              void* d_out, int out_size)
{
    const float* coords = (const float*)d_in[0];
    const float* Wf     = (const float*)d_in[1];
    const float* bf     = (const float*)d_in[2];
    const float* Wh     = (const float*)d_in[3];
    const float* bh     = (const float*)d_in[4];
    const float* Wl     = (const float*)d_in[5];
    const float* bl     = (const float*)d_in[6];
    float* out = (float*)d_out;

    const int N = in_sizes[0] / IN_F;   // 524288
    const int blocks = (N + TPB - 1) / TPB;
    siren_kernel<<<blocks, TPB>>>(coords, Wf, bf, Wh, bh, Wl, bl, out, N);
}

// round 3
// speedup vs baseline: 1.7543x; 1.7543x over previous
#include <cuda_runtime.h>

// SIREN: N pts, 3 -> 5 (sine) -> 256 x [5 -> 5 (sine)] -> 1 linear.
// Output: [out (N) | coords passthrough (3N)].
// 2 points per thread packed in f32x2 (FFMA2) registers.

typedef unsigned long long u64;
typedef unsigned int u32;

static constexpr int IN_F  = 3;
static constexpr int HID   = 5;
static constexpr int N_HID = 256;
static constexpr float OMEGA = 30.0f;
static constexpr int TPB = 256;

// dynamic smem layout (floats):
//   [0, 16384)     : 256 layers x 64 floats (30 dup pairs: 25 w-pairs p=k*5+j, 5 b-pairs p=25+j, 4 pad)
//   [16384, 16424) : first layer, 20 dup pairs (15 w-pairs p=c*5+j, 5 b-pairs p=15+j)
//   [16424, 16436) : final, 5 w-pairs + 1 b-pair
static constexpr int SMEM_FLOATS = N_HID * 64 + 40 + 12;
static constexpr int SMEM_BYTES  = SMEM_FLOATS * 4;

__device__ __forceinline__ u64 fma2(u64 a, u64 b, u64 c) {
    u64 d; asm("fma.rn.f32x2 %0, %1, %2, %3;" : "=l"(d) : "l"(a), "l"(b), "l"(c)); return d;
}
__device__ __forceinline__ u64 add2(u64 a, u64 b) {
    u64 d; asm("add.rn.f32x2 %0, %1, %2;" : "=l"(d) : "l"(a), "l"(b)); return d;
}
__device__ __forceinline__ u64 mul2(u64 a, u64 b) {
    u64 d; asm("mul.rn.f32x2 %0, %1, %2;" : "=l"(d) : "l"(a), "l"(b)); return d;
}
__device__ __forceinline__ u64 pack2(float a, float b) {
    u64 d; asm("mov.b64 %0, {%1, %2};" : "=l"(d) : "f"(a), "f"(b)); return d;
}
__device__ __forceinline__ float2 unpack2(u64 d) {
    float2 f; asm("mov.b64 {%0, %1}, %2;" : "=f"(f.x), "=f"(f.y) : "l"(d)); return f;
}

struct SinK {
    u64 magic, nmagic, invpi, npi1, npi2, c11, c9, c7, c5, c3;
};

// sin on both packed lanes. |x| <= ~50. fj = rint(x/pi) via magic add,
// r = x - fj*pi (2-term Cody-Waite), deg-11 minimax on [-pi/2,pi/2],
// sign flip (-1)^fj via parity bit of the magic-biased float.
__device__ __forceinline__ u64 sin2(u64 x, const SinK& K) {
    u64 t  = fma2(x, K.invpi, K.magic);
    u64 fj = add2(t, K.nmagic);
    u64 r  = fma2(fj, K.npi1, x);
    r      = fma2(fj, K.npi2, r);
    u64 r2 = mul2(r, r);
    u64 p  = fma2(r2, K.c11, K.c9);
    p      = fma2(r2, p, K.c7);
    p      = fma2(r2, p, K.c5);
    p      = fma2(r2, p, K.c3);
    u64 r3 = mul2(r, r2);
    u64 s  = fma2(r3, p, r);
    // sign: bit0 of each magic-biased half -> sign bit (ALU pipe: SHF/LOP3)
    u32 slo = (u32)s ^ ((u32)t << 31);
    u32 shi = (u32)(s >> 32) ^ ((u32)(t >> 32) << 31);
    return ((u64)shi << 32) | slo;
}

__global__ void __launch_bounds__(TPB)
siren_kernel(const float* __restrict__ coords,
             const float* __restrict__ Wf, const float* __restrict__ bf,
             const float* __restrict__ Wh, const float* __restrict__ bh,
             const float* __restrict__ Wl, const float* __restrict__ bl,
             float* __restrict__ out, int N)
{
    extern __shared__ float smem[];
    float* blob = smem;
    float* fst  = smem + N_HID * 64;
    float* fin  = fst + 40;

    const int tid = threadIdx.x;
    for (int idx = tid; idx < N_HID * 25; idx += TPB) {
        int l = idx / 25, r = idx % 25;
        int j = r / 5, k = r % 5;
        float v = OMEGA * Wh[idx];
        int o = l * 64 + (k * 5 + j) * 2;
        blob[o] = v; blob[o + 1] = v;
    }
    for (int idx = tid; idx < N_HID * 5; idx += TPB) {
        int l = idx / 5, j = idx % 5;
        float v = OMEGA * bh[idx];
        int o = l * 64 + (25 + j) * 2;
        blob[o] = v; blob[o + 1] = v;
    }
    if (tid < 15) {
        int j = tid / 3, c = tid % 3;
        float v = OMEGA * Wf[tid];
        int o = (c * 5 + j) * 2;
        fst[o] = v; fst[o + 1] = v;
    }
    if (tid < 5) { float v = OMEGA * bf[tid]; int o = (15 + tid) * 2; fst[o] = v; fst[o + 1] = v; }
    if (tid < 5) { float v = Wl[tid]; fin[2 * tid] = v; fin[2 * tid + 1] = v; }
    if (tid == 0) { fin[10] = bl[0]; fin[11] = bl[0]; }
    __syncthreads();

    const int g = blockIdx.x * TPB + tid;      // pair index: points 2g, 2g+1
    if (2 * g >= N) return;

    SinK K;
    K.magic  = pack2( 12582912.0f,  12582912.0f);
    K.nmagic = pack2(-12582912.0f, -12582912.0f);
    K.invpi  = pack2( 0.318309886183790672f,  0.318309886183790672f);
    K.npi1   = pack2(-3.14159250259399414e+0f, -3.14159250259399414e+0f);
    K.npi2   = pack2(-1.50995788317173719e-7f, -1.50995788317173719e-7f);
    K.c11    = pack2(-2.3828544692960918e-8f, -2.3828544692960918e-8f);
    K.c9     = pack2( 2.7521557770526783e-6f,  2.7521557770526783e-6f);
    K.c7     = pack2(-1.9840782426250314e-4f, -1.9840782426250314e-4f);
    K.c5     = pack2( 8.3330835227672527e-3f,  8.3330835227672527e-3f);
    K.c3     = pack2(-1.6666648387364197e-1f, -1.6666648387364197e-1f);

    // coords: 6 consecutive floats per thread -> 3x LDG.64
    const float2* c2p = (const float2*)coords;
    float2 v0 = c2p[3 * g + 0];   // c0A, c1A
    float2 v1 = c2p[3 * g + 1];   // c2A, c0B
    float2 v2 = c2p[3 * g + 2];   // c1B, c2B
    u64 cp0 = pack2(v0.x, v1.y);
    u64 cp1 = pack2(v0.y, v2.x);
    u64 cp2 = pack2(v1.x, v2.y);

    // first layer
    u64 x0, x1, x2, x3, x4;
    {
        const u64* F = (const u64*)fst;
        u64 y0 = F[15], y1 = F[16], y2 = F[17], y3 = F[18], y4 = F[19];
        y0 = fma2(F[0], cp0, y0);  y1 = fma2(F[1], cp0, y1);
        y2 = fma2(F[2], cp0, y2);  y3 = fma2(F[3], cp0, y3);
        y4 = fma2(F[4], cp0, y4);
        y0 = fma2(F[5], cp1, y0);  y1 = fma2(F[6], cp1, y1);
        y2 = fma2(F[7], cp1, y2);  y3 = fma2(F[8], cp1, y3);
        y4 = fma2(F[9], cp1, y4);
        y0 = fma2(F[10], cp2, y0); y1 = fma2(F[11], cp2, y1);
        y2 = fma2(F[12], cp2, y2); y3 = fma2(F[13], cp2, y3);
        y4 = fma2(F[14], cp2, y4);
        x0 = sin2(y0, K); x1 = sin2(y1, K); x2 = sin2(y2, K);
        x3 = sin2(y3, K); x4 = sin2(y4, K);
    }

    // 256 hidden layers
    const u64* Lp = (const u64*)blob;
#pragma unroll 1
    for (int l = 0; l < N_HID; l++) {
        u64 y0 = Lp[25], y1 = Lp[26], y2 = Lp[27], y3 = Lp[28], y4 = Lp[29];
        // k = 0..4 hand-expanded: direct register refs, no select chains
        y0 = fma2(Lp[ 0], x0, y0); y1 = fma2(Lp[ 1], x0, y1);
        y2 = fma2(Lp[ 2], x0, y2); y3 = fma2(Lp[ 3], x0, y3);
        y4 = fma2(Lp[ 4], x0, y4);
        y0 = fma2(Lp[ 5], x1, y0); y1 = fma2(Lp[ 6], x1, y1);
        y2 = fma2(Lp[ 7], x1, y2); y3 = fma2(Lp[ 8], x1, y3);
        y4 = fma2(Lp[ 9], x1, y4);
        y0 = fma2(Lp[10], x2, y0); y1 = fma2(Lp[11], x2, y1);
        y2 = fma2(Lp[12], x2, y2); y3 = fma2(Lp[13], x2, y3);
        y4 = fma2(Lp[14], x2, y4);
        y0 = fma2(Lp[15], x3, y0); y1 = fma2(Lp[16], x3, y1);
        y2 = fma2(Lp[17], x3, y2); y3 = fma2(Lp[18], x3, y3);
        y4 = fma2(Lp[19], x3, y4);
        y0 = fma2(Lp[20], x4, y0); y1 = fma2(Lp[21], x4, y1);
        y2 = fma2(Lp[22], x4, y2); y3 = fma2(Lp[23], x4, y3);
        y4 = fma2(Lp[24], x4, y4);
        x0 = sin2(y0, K); x1 = sin2(y1, K); x2 = sin2(y2, K);
        x3 = sin2(y3, K); x4 = sin2(y4, K);
        Lp += 32;
    }

    // final linear
    const u64* G = (const u64*)fin;
    u64 o = G[5];
    o = fma2(G[0], x0, o);
    o = fma2(G[1], x1, o);
    o = fma2(G[2], x2, o);
    o = fma2(G[3], x3, o);
    o = fma2(G[4], x4, o);

    ((float2*)out)[g] = unpack2(o);

    // coords passthrough
    float2* cpass = (float2*)(out + N);
    cpass[3 * g + 0] = v0;
    cpass[3 * g + 1] = v1;
    cpass[3 * g + 2] = v2;
}

extern "C" void kernel_launch(void* const* d_in, const int* in_sizes, int n_in,
                              void* d_out, int out_size)
{
    const float* coords = (const float*)d_in[0];
    const float* Wf     = (const float*)d_in[1];
    const float* bf     = (const float*)d_in[2];
    const float* Wh     = (const float*)d_in[3];
    const float* bh     = (const float*)d_in[4];
    const float* Wl     = (const float*)d_in[5];
    const float* bl     = (const float*)d_in[6];
    float* out = (float*)d_out;

    const int N = in_sizes[0] / IN_F;               // 524288
    const int pairs = N / 2;                        // 2 pts per thread
    const int blocks = (pairs + TPB - 1) / TPB;

    cudaFuncSetAttribute(siren_kernel, cudaFuncAttributeMaxDynamicSharedMemorySize, SMEM_BYTES);
    siren_kernel<<<blocks, TPB, SMEM_BYTES>>>(coords, Wf, bf, Wh, bh, Wl, bl, out, N);
}

// round 4
// speedup vs baseline: 2.0671x; 1.1783x over previous
#include <cuda_runtime.h>

// SIREN: N pts, 3 -> 5 (sine) -> 256 x [5 -> 5 (sine)] -> 1 linear.
// Output: [out (N) | coords passthrough (3N)].
// 4 points/thread as 2 f32x2 packs. Matvec + pi-reduction on FMA pipe (FFMA2),
// sine core offloaded to MUFU (sin.approx) with sign pre-applied via oddness.

typedef unsigned long long u64;
typedef unsigned int u32;

static constexpr int IN_F  = 3;
static constexpr int HID   = 5;
static constexpr int N_HID = 256;
static constexpr float OMEGA = 30.0f;
static constexpr int TPB = 256;

// dynamic smem (floats):
//   [0, 16384)     : 256 layers x 64 (30 dup pairs: 25 w p=k*5+j, 5 b p=25+j)
//   [16384, 16424) : first layer 20 dup pairs
//   [16424, 16436) : final 5 w-pairs + 1 b-pair
static constexpr int SMEM_FLOATS = N_HID * 64 + 40 + 12;
static constexpr int SMEM_BYTES  = SMEM_FLOATS * 4;

__device__ __forceinline__ u64 fma2(u64 a, u64 b, u64 c) {
    u64 d; asm("fma.rn.f32x2 %0, %1, %2, %3;" : "=l"(d) : "l"(a), "l"(b), "l"(c)); return d;
}
__device__ __forceinline__ u64 add2(u64 a, u64 b) {
    u64 d; asm("add.rn.f32x2 %0, %1, %2;" : "=l"(d) : "l"(a), "l"(b)); return d;
}
__device__ __forceinline__ u64 pack2(float a, float b) {
    u64 d; asm("mov.b64 %0, {%1, %2};" : "=l"(d) : "f"(a), "f"(b)); return d;
}
__device__ __forceinline__ float2 unpack2(u64 d) {
    float2 f; asm("mov.b64 {%0, %1}, %2;" : "=f"(f.x), "=f"(f.y) : "l"(d)); return f;
}
__device__ __forceinline__ float sinap(float x) {
    float s; asm("sin.approx.f32 %0, %1;" : "=f"(s) : "f"(x)); return s;
}

struct SinK { u64 magic, nmagic, invpi, npi1, npi2; };

// sin of both packed lanes: exact CW pi-reduction (FMA pipe) + MUFU sine.
// sin(y) = (-1)^fj sin(r) = sin((-1)^fj r)  [oddness]; parity = bit0 of magic-biased t.
__device__ __forceinline__ u64 sin2m(u64 y, const SinK& K) {
    u64 t  = fma2(y, K.invpi, K.magic);
    u64 fj = add2(t, K.nmagic);
    u64 r  = fma2(fj, K.npi1, y);
    r      = fma2(fj, K.npi2, r);
    u32 rl = (u32)r          ^ ((u32)t          << 31);
    u32 rh = (u32)(r >> 32)  ^ ((u32)(t >> 32)  << 31);
    float sl = sinap(__uint_as_float(rl));
    float sh = sinap(__uint_as_float(rh));
    return pack2(sl, sh);
}

__global__ void __launch_bounds__(TPB)
siren_kernel(const float* __restrict__ coords,
             const float* __restrict__ Wf, const float* __restrict__ bf,
             const float* __restrict__ Wh, const float* __restrict__ bh,
             const float* __restrict__ Wl, const float* __restrict__ bl,
             float* __restrict__ out, int N)
{
    extern __shared__ float smem[];
    float* blob = smem;
    float* fst  = smem + N_HID * 64;
    float* fin  = fst + 40;

    const int tid = threadIdx.x;
    for (int idx = tid; idx < N_HID * 25; idx += TPB) {
        int l = idx / 25, r = idx % 25;
        int j = r / 5, k = r % 5;
        float v = OMEGA * Wh[idx];
        int o = l * 64 + (k * 5 + j) * 2;
        blob[o] = v; blob[o + 1] = v;
    }
    for (int idx = tid; idx < N_HID * 5; idx += TPB) {
        int l = idx / 5, j = idx % 5;
        float v = OMEGA * bh[idx];
        int o = l * 64 + (25 + j) * 2;
        blob[o] = v; blob[o + 1] = v;
    }
    if (tid < 15) {
        int j = tid / 3, c = tid % 3;
        float v = OMEGA * Wf[tid];
        int o = (c * 5 + j) * 2;
        fst[o] = v; fst[o + 1] = v;
    }
    if (tid < 5) { float v = OMEGA * bf[tid]; int o = (15 + tid) * 2; fst[o] = v; fst[o + 1] = v; }
    if (tid < 5) { float v = Wl[tid]; fin[2 * tid] = v; fin[2 * tid + 1] = v; }
    if (tid == 0) { fin[10] = bl[0]; fin[11] = bl[0]; }
    __syncthreads();

    const int g = blockIdx.x * TPB + tid;      // quad index: points 4g..4g+3
    if (4 * g >= N) return;

    SinK K;
    K.magic  = pack2( 12582912.0f,  12582912.0f);
    K.nmagic = pack2(-12582912.0f, -12582912.0f);
    K.invpi  = pack2( 0.318309886183790672f,  0.318309886183790672f);
    K.npi1   = pack2(-3.14159250259399414e+0f, -3.14159250259399414e+0f);
    K.npi2   = pack2(-1.50995788317173719e-7f, -1.50995788317173719e-7f);

    // coords: 12 consecutive floats -> 3x LDG.128
    const float4* c4p = (const float4*)coords;
    float4 q0 = c4p[3 * g + 0];   // c0A c1A c2A c0B
    float4 q1 = c4p[3 * g + 1];   // c1B c2B c0C c1C
    float4 q2 = c4p[3 * g + 2];   // c2C c0D c1D c2D
    u64 a_c0 = pack2(q0.x, q0.w);  // pack A,B
    u64 a_c1 = pack2(q0.y, q1.x);
    u64 a_c2 = pack2(q0.z, q1.y);
    u64 b_c0 = pack2(q1.z, q2.y);  // pack C,D
    u64 b_c1 = pack2(q1.w, q2.z);
    u64 b_c2 = pack2(q2.x, q2.w);

    u64 xa0, xa1, xa2, xa3, xa4, xb0, xb1, xb2, xb3, xb4;
    {   // first layer, both packs
        const u64* F = (const u64*)fst;
        u64 w;
        u64 ya0 = F[15], ya1 = F[16], ya2 = F[17], ya3 = F[18], ya4 = F[19];
        u64 yb0 = ya0, yb1 = ya1, yb2 = ya2, yb3 = ya3, yb4 = ya4;
        w = F[0];  ya0 = fma2(w, a_c0, ya0); yb0 = fma2(w, b_c0, yb0);
        w = F[1];  ya1 = fma2(w, a_c0, ya1); yb1 = fma2(w, b_c0, yb1);
        w = F[2];  ya2 = fma2(w, a_c0, ya2); yb2 = fma2(w, b_c0, yb2);
        w = F[3];  ya3 = fma2(w, a_c0, ya3); yb3 = fma2(w, b_c0, yb3);
        w = F[4];  ya4 = fma2(w, a_c0, ya4); yb4 = fma2(w, b_c0, yb4);
        w = F[5];  ya0 = fma2(w, a_c1, ya0); yb0 = fma2(w, b_c1, yb0);
        w = F[6];  ya1 = fma2(w, a_c1, ya1); yb1 = fma2(w, b_c1, yb1);
        w = F[7];  ya2 = fma2(w, a_c1, ya2); yb2 = fma2(w, b_c1, yb2);
        w = F[8];  ya3 = fma2(w, a_c1, ya3); yb3 = fma2(w, b_c1, yb3);
        w = F[9];  ya4 = fma2(w, a_c1, ya4); yb4 = fma2(w, b_c1, yb4);
        w = F[10]; ya0 = fma2(w, a_c2, ya0); yb0 = fma2(w, b_c2, yb0);
        w = F[11]; ya1 = fma2(w, a_c2, ya1); yb1 = fma2(w, b_c2, yb1);
        w = F[12]; ya2 = fma2(w, a_c2, ya2); yb2 = fma2(w, b_c2, yb2);
        w = F[13]; ya3 = fma2(w, a_c2, ya3); yb3 = fma2(w, b_c2, yb3);
        w = F[14]; ya4 = fma2(w, a_c2, ya4); yb4 = fma2(w, b_c2, yb4);
        xa0 = sin2m(ya0, K); xa1 = sin2m(ya1, K); xa2 = sin2m(ya2, K);
        xa3 = sin2m(ya3, K); xa4 = sin2m(ya4, K);
        xb0 = sin2m(yb0, K); xb1 = sin2m(yb1, K); xb2 = sin2m(yb2, K);
        xb3 = sin2m(yb3, K); xb4 = sin2m(yb4, K);
    }

    // 256 hidden layers
    const u64* Lp = (const u64*)blob;
#pragma unroll 1
    for (int l = 0; l < N_HID; l++) {
        u64 w;
        u64 ya0 = Lp[25], ya1 = Lp[26], ya2 = Lp[27], ya3 = Lp[28], ya4 = Lp[29];
        u64 yb0 = ya0, yb1 = ya1, yb2 = ya2, yb3 = ya3, yb4 = ya4;
        w = Lp[ 0]; ya0 = fma2(w, xa0, ya0); yb0 = fma2(w, xb0, yb0);
        w = Lp[ 1]; ya1 = fma2(w, xa0, ya1); yb1 = fma2(w, xb0, yb1);
        w = Lp[ 2]; ya2 = fma2(w, xa0, ya2); yb2 = fma2(w, xb0, yb2);
        w = Lp[ 3]; ya3 = fma2(w, xa0, ya3); yb3 = fma2(w, xb0, yb3);
        w = Lp[ 4]; ya4 = fma2(w, xa0, ya4); yb4 = fma2(w, xb0, yb4);
        w = Lp[ 5]; ya0 = fma2(w, xa1, ya0); yb0 = fma2(w, xb1, yb0);
        w = Lp[ 6]; ya1 = fma2(w, xa1, ya1); yb1 = fma2(w, xb1, yb1);
        w = Lp[ 7]; ya2 = fma2(w, xa1, ya2); yb2 = fma2(w, xb1, yb2);
        w = Lp[ 8]; ya3 = fma2(w, xa1, ya3); yb3 = fma2(w, xb1, yb3);
        w = Lp[ 9]; ya4 = fma2(w, xa1, ya4); yb4 = fma2(w, xb1, yb4);
        w = Lp[10]; ya0 = fma2(w, xa2, ya0); yb0 = fma2(w, xb2, yb0);
        w = Lp[11]; ya1 = fma2(w, xa2, ya1); yb1 = fma2(w, xb2, yb1);
        w = Lp[12]; ya2 = fma2(w, xa2, ya2); yb2 = fma2(w, xb2, yb2);
        w = Lp[13]; ya3 = fma2(w, xa2, ya3); yb3 = fma2(w, xb2, yb3);
        w = Lp[14]; ya4 = fma2(w, xa2, ya4); yb4 = fma2(w, xb2, yb4);
        w = Lp[15]; ya0 = fma2(w, xa3, ya0); yb0 = fma2(w, xb3, yb0);
        w = Lp[16]; ya1 = fma2(w, xa3, ya1); yb1 = fma2(w, xb3, yb1);
        w = Lp[17]; ya2 = fma2(w, xa3, ya2); yb2 = fma2(w, xb3, yb2);
        w = Lp[18]; ya3 = fma2(w, xa3, ya3); yb3 = fma2(w, xb3, yb3);
        w = Lp[19]; ya4 = fma2(w, xa3, ya4); yb4 = fma2(w, xb3, yb4);
        w = Lp[20]; ya0 = fma2(w, xa4, ya0); yb0 = fma2(w, xb4, yb0);
        w = Lp[21]; ya1 = fma2(w, xa4, ya1); yb1 = fma2(w, xb4, yb1);
        w = Lp[22]; ya2 = fma2(w, xa4, ya2); yb2 = fma2(w, xb4, yb2);
        w = Lp[23]; ya3 = fma2(w, xa4, ya3); yb3 = fma2(w, xb4, yb3);
        w = Lp[24]; ya4 = fma2(w, xa4, ya4); yb4 = fma2(w, xb4, yb4);
        xa0 = sin2m(ya0, K); xa1 = sin2m(ya1, K); xa2 = sin2m(ya2, K);
        xa3 = sin2m(ya3, K); xa4 = sin2m(ya4, K);
        xb0 = sin2m(yb0, K); xb1 = sin2m(yb1, K); xb2 = sin2m(yb2, K);
        xb3 = sin2m(yb3, K); xb4 = sin2m(yb4, K);
        Lp += 32;
    }

    // final linear
    const u64* G = (const u64*)fin;
    u64 oa = G[5], ob = G[5];
    oa = fma2(G[0], xa0, oa); ob = fma2(G[0], xb0, ob);
    oa = fma2(G[1], xa1, oa); ob = fma2(G[1], xb1, ob);
    oa = fma2(G[2], xa2, oa); ob = fma2(G[2], xb2, ob);
    oa = fma2(G[3], xa3, oa); ob = fma2(G[3], xb3, ob);
    oa = fma2(G[4], xa4, oa); ob = fma2(G[4], xb4, ob);

    float2 fa = unpack2(oa), fb = unpack2(ob);
    ((float4*)out)[g] = make_float4(fa.x, fa.y, fb.x, fb.y);

    // coords passthrough
    float4* cpass = (float4*)(out + N);
    cpass[3 * g + 0] = q0;
    cpass[3 * g + 1] = q1;
    cpass[3 * g + 2] = q2;
}

extern "C" void kernel_launch(void* const* d_in, const int* in_sizes, int n_in,
                              void* d_out, int out_size)
{
    const float* coords = (const float*)d_in[0];
    const float* Wf     = (const float*)d_in[1];
    const float* bf     = (const float*)d_in[2];
    const float* Wh     = (const float*)d_in[3];
    const float* bh     = (const float*)d_in[4];
    const float* Wl     = (const float*)d_in[5];
    const float* bl     = (const float*)d_in[6];
    float* out = (float*)d_out;

    const int N = in_sizes[0] / IN_F;               // 524288
    const int quads = N / 4;                        // 4 pts per thread
    const int blocks = (quads + TPB - 1) / TPB;     // 512

    cudaFuncSetAttribute(siren_kernel, cudaFuncAttributeMaxDynamicSharedMemorySize, SMEM_BYTES);
    siren_kernel<<<blocks, TPB, SMEM_BYTES>>>(coords, Wf, bf, Wh, bh, Wl, bl, out, N);
}

// round 5
// speedup vs baseline: 2.2546x; 1.0907x over previous
#include <cuda_runtime.h>

// SIREN: N pts, 3 -> 5 (sine) -> 256 x [5 -> 5 (sine)] -> 1 linear.
// Output: [out (N) | coords passthrough (3N)].
// 4 pts/thread as 2 f32x2 packs. FFMA2 matvec + 1-term CW mod-2pi reduction,
// MUFU sin.approx core (arg in [-pi,pi], no sign fixup).
// Weights: 25 dup-pairs/layer in smem; biases scalar (splat, fma addend).

typedef unsigned long long u64;
typedef unsigned int u32;

static constexpr int IN_F  = 3;
static constexpr int HID   = 5;
static constexpr int N_HID = 256;
static constexpr float OMEGA = 30.0f;
static constexpr int TPB = 256;

// smem: [0, 51200) 256 layers x 25 w-pairs (u64);  [51200, 56320) 256 x 5 bias scalars
static constexpr int BLOB_U64   = N_HID * 25;
static constexpr int SMEM_BYTES = BLOB_U64 * 8 + N_HID * 5 * 4;   // 56320

__device__ __forceinline__ u64 fma2(u64 a, u64 b, u64 c) {
    u64 d; asm("fma.rn.f32x2 %0, %1, %2, %3;" : "=l"(d) : "l"(a), "l"(b), "l"(c)); return d;
}
__device__ __forceinline__ u64 add2(u64 a, u64 b) {
    u64 d; asm("add.rn.f32x2 %0, %1, %2;" : "=l"(d) : "l"(a), "l"(b)); return d;
}
__device__ __forceinline__ u64 pack2(float a, float b) {
    u64 d; asm("mov.b64 %0, {%1, %2};" : "=l"(d) : "f"(a), "f"(b)); return d;
}
__device__ __forceinline__ u64 splat2(float a) {
    u64 d; asm("mov.b64 %0, {%1, %1};" : "=l"(d) : "f"(a)); return d;
}
__device__ __forceinline__ float2 unpack2(u64 d) {
    float2 f; asm("mov.b64 {%0, %1}, %2;" : "=f"(f.x), "=f"(f.y) : "l"(d)); return f;
}
__device__ __forceinline__ float sinap(float x) {
    float s; asm("sin.approx.f32 %0, %1;" : "=f"(s) : "f"(x)); return s;
}

struct SinK { u64 magic, nmagic, inv2pi, n2pi; };

// sin of both lanes: 1-term CW reduction mod 2pi into [-pi,pi], MUFU sine.
__device__ __forceinline__ u64 sin2m(u64 y, const SinK& K) {
    u64 t  = fma2(y, K.inv2pi, K.magic);
    u64 fj = add2(t, K.nmagic);
    u64 r  = fma2(fj, K.n2pi, y);
    float2 rf = unpack2(r);
    return pack2(sinap(rf.x), sinap(rf.y));
}

__global__ void __launch_bounds__(TPB, 4)
siren_kernel(const float* __restrict__ coords,
             const float* __restrict__ Wf, const float* __restrict__ bf,
             const float* __restrict__ Wh, const float* __restrict__ bh,
             const float* __restrict__ Wl, const float* __restrict__ bl,
             float* __restrict__ out, int N)
{
    extern __shared__ float smem[];
    u64*   wp = (u64*)smem;                  // 25 pairs per layer, stride 25 u64
    float* bp = smem + BLOB_U64 * 2;         // 5 scalars per layer

    const int tid = threadIdx.x;
    for (int idx = tid; idx < N_HID * 25; idx += TPB) {
        int l = idx / 25, r = idx % 25;
        int j = r / 5, k = r % 5;
        wp[l * 25 + k * 5 + j] = splat2(OMEGA * Wh[l * 25 + j * 5 + k]);
    }
    for (int idx = tid; idx < N_HID * 5; idx += TPB) {
        bp[idx] = OMEGA * bh[idx];
    }
    __syncthreads();

    const int g = blockIdx.x * TPB + tid;    // quad index: points 4g..4g+3 (exact fit)

    SinK K;
    K.magic  = splat2( 12582912.0f);
    K.nmagic = splat2(-12582912.0f);
    K.inv2pi = splat2( 0.15915494309189535f);
    K.n2pi   = splat2(-6.28318530717958648f);

    // coords: 12 consecutive floats -> 3x LDG.128; passthrough stored immediately
    const float4* c4p = (const float4*)coords;
    float4 q0 = c4p[3 * g + 0];   // c0A c1A c2A c0B
    float4 q1 = c4p[3 * g + 1];   // c1B c2B c0C c1C
    float4 q2 = c4p[3 * g + 2];   // c2C c0D c1D c2D
    float4* cpass = (float4*)(out + N);
    cpass[3 * g + 0] = q0;
    cpass[3 * g + 1] = q1;
    cpass[3 * g + 2] = q2;

    u64 a_c0 = pack2(q0.x, q0.w);  // points A,B
    u64 a_c1 = pack2(q0.y, q1.x);
    u64 a_c2 = pack2(q0.z, q1.y);
    u64 b_c0 = pack2(q1.z, q2.y);  // points C,D
    u64 b_c1 = pack2(q1.w, q2.z);
    u64 b_c2 = pack2(q2.x, q2.w);

    // first layer: weights direct from global (L2 broadcast, cold path)
    u64 xa0, xa1, xa2, xa3, xa4, xb0, xb1, xb2, xb3, xb4;
    {
        u64 ya[HID], yb[HID];
#pragma unroll
        for (int j = 0; j < HID; j++) {
            u64 bj = splat2(OMEGA * bf[j]);
            u64 w0 = splat2(OMEGA * Wf[j * IN_F + 0]);
            u64 w1 = splat2(OMEGA * Wf[j * IN_F + 1]);
            u64 w2 = splat2(OMEGA * Wf[j * IN_F + 2]);
            u64 ya_j = fma2(w0, a_c0, bj);
            u64 yb_j = fma2(w0, b_c0, bj);
            ya_j = fma2(w1, a_c1, ya_j);  yb_j = fma2(w1, b_c1, yb_j);
            ya_j = fma2(w2, a_c2, ya_j);  yb_j = fma2(w2, b_c2, yb_j);
            ya[j] = ya_j; yb[j] = yb_j;
        }
        xa0 = sin2m(ya[0], K); xa1 = sin2m(ya[1], K); xa2 = sin2m(ya[2], K);
        xa3 = sin2m(ya[3], K); xa4 = sin2m(ya[4], K);
        xb0 = sin2m(yb[0], K); xb1 = sin2m(yb[1], K); xb2 = sin2m(yb[2], K);
        xb3 = sin2m(yb[3], K); xb4 = sin2m(yb[4], K);
    }

    // 256 hidden layers
    const u64*   L = wp;
    const float* B = bp;
#pragma unroll 1
    for (int l = 0; l < N_HID; l++) {
        u64 w;
        u64 b0 = splat2(B[0]), b1 = splat2(B[1]), b2 = splat2(B[2]),
            b3 = splat2(B[3]), b4 = splat2(B[4]);
        // k=0 row: bias as fma addend (no y-init copies)
        u64 ya0, ya1, ya2, ya3, ya4, yb0, yb1, yb2, yb3, yb4;
        w = L[ 0]; ya0 = fma2(w, xa0, b0); yb0 = fma2(w, xb0, b0);
        w = L[ 1]; ya1 = fma2(w, xa0, b1); yb1 = fma2(w, xb0, b1);
        w = L[ 2]; ya2 = fma2(w, xa0, b2); yb2 = fma2(w, xb0, b2);
        w = L[ 3]; ya3 = fma2(w, xa0, b3); yb3 = fma2(w, xb0, b3);
        w = L[ 4]; ya4 = fma2(w, xa0, b4); yb4 = fma2(w, xb0, b4);
        w = L[ 5]; ya0 = fma2(w, xa1, ya0); yb0 = fma2(w, xb1, yb0);
        w = L[ 6]; ya1 = fma2(w, xa1, ya1); yb1 = fma2(w, xb1, yb1);
        w = L[ 7]; ya2 = fma2(w, xa1, ya2); yb2 = fma2(w, xb1, yb2);
        w = L[ 8]; ya3 = fma2(w, xa1, ya3); yb3 = fma2(w, xb1, yb3);
        w = L[ 9]; ya4 = fma2(w, xa1, ya4); yb4 = fma2(w, xb1, yb4);
        w = L[10]; ya0 = fma2(w, xa2, ya0); yb0 = fma2(w, xb2, yb0);
        w = L[11]; ya1 = fma2(w, xa2, ya1); yb1 = fma2(w, xb2, yb1);
        w = L[12]; ya2 = fma2(w, xa2, ya2); yb2 = fma2(w, xb2, yb2);
        w = L[13]; ya3 = fma2(w, xa2, ya3); yb3 = fma2(w, xb2, yb3);
        w = L[14]; ya4 = fma2(w, xa2, ya4); yb4 = fma2(w, xb2, yb4);
        w = L[15]; ya0 = fma2(w, xa3, ya0); yb0 = fma2(w, xb3, yb0);
        w = L[16]; ya1 = fma2(w, xa3, ya1); yb1 = fma2(w, xb3, yb1);
        w = L[17]; ya2 = fma2(w, xa3, ya2); yb2 = fma2(w, xb3, yb2);
        w = L[18]; ya3 = fma2(w, xa3, ya3); yb3 = fma2(w, xb3, yb3);
        w = L[19]; ya4 = fma2(w, xa3, ya4); yb4 = fma2(w, xb3, yb4);
        w = L[20]; ya0 = fma2(w, xa4, ya0); yb0 = fma2(w, xb4, yb0);
        w = L[21]; ya1 = fma2(w, xa4, ya1); yb1 = fma2(w, xb4, yb1);
        w = L[22]; ya2 = fma2(w, xa4, ya2); yb2 = fma2(w, xb4, yb2);
        w = L[23]; ya3 = fma2(w, xa4, ya3); yb3 = fma2(w, xb4, yb3);
        w = L[24]; ya4 = fma2(w, xa4, ya4); yb4 = fma2(w, xb4, yb4);
        xa0 = sin2m(ya0, K); xa1 = sin2m(ya1, K); xa2 = sin2m(ya2, K);
        xa3 = sin2m(ya3, K); xa4 = sin2m(ya4, K);
        xb0 = sin2m(yb0, K); xb1 = sin2m(yb1, K); xb2 = sin2m(yb2, K);
        xb3 = sin2m(yb3, K); xb4 = sin2m(yb4, K);
        L += 25;
        B += 5;
    }

    // final linear: weights direct from global
    u64 g0 = splat2(Wl[0]), g1 = splat2(Wl[1]), g2 = splat2(Wl[2]),
        g3 = splat2(Wl[3]), g4 = splat2(Wl[4]);
    u64 ob0 = splat2(bl[0]);
    u64 oa = fma2(g0, xa0, ob0), ob = fma2(g0, xb0, ob0);
    oa = fma2(g1, xa1, oa); ob = fma2(g1, xb1, ob);
    oa = fma2(g2, xa2, oa); ob = fma2(g2, xb2, ob);
    oa = fma2(g3, xa3, oa); ob = fma2(g3, xb3, ob);
    oa = fma2(g4, xa4, oa); ob = fma2(g4, xb4, ob);

    float2 fa = unpack2(oa), fb = unpack2(ob);
    ((float4*)out)[g] = make_float4(fa.x, fa.y, fb.x, fb.y);
}

extern "C" void kernel_launch(void* const* d_in, const int* in_sizes, int n_in,
                              void* d_out, int out_size)
{
    const float* coords = (const float*)d_in[0];
    const float* Wf     = (const float*)d_in[1];
    const float* bf     = (const float*)d_in[2];
    const float* Wh     = (const float*)d_in[3];
    const float* bh     = (const float*)d_in[4];
    const float* Wl     = (const float*)d_in[5];
    const float* bl     = (const float*)d_in[6];
    float* out = (float*)d_out;

    const int N = in_sizes[0] / IN_F;               // 524288
    const int quads = N / 4;                        // 131072
    const int blocks = quads / TPB;                 // 512, exact

    cudaFuncSetAttribute(siren_kernel, cudaFuncAttributeMaxDynamicSharedMemorySize, SMEM_BYTES);
    siren_kernel<<<blocks, TPB, SMEM_BYTES>>>(coords, Wf, bf, Wh, bh, Wl, bl, out, N);
}